// round 17
// baseline (speedup 1.0000x reference)
#include <cuda_runtime.h>
#include <cuda_fp16.h>
#include <cstdint>

// Problem constants
#define T_STEPS 100
#define BATCH   64
#define M_DIM   (T_STEPS * BATCH)   // 6400
#define N_DIM   1024
#define K_DIM   1024
#define KP      (K_DIM / 2)         // 512 packed fp16x2 per row
#define THR     15.0f

// scratch
__device__ float    g_delta[(size_t)M_DIM * N_DIM];     // 26 MB
__device__ uint32_t g_Apk [(size_t)M_DIM * KP];         // spikes as fp16x2, 13 MB
__device__ uint32_t g_Wh  [(size_t)N_DIM * KP];         // W hi (fp16x2), 2 MB
__device__ uint32_t g_Wl  [(size_t)N_DIM * KP];         // W lo residual (fp16x2)

// ---------------------------------------------------------------------------
// Prep: exact 2-way fp16 split of W (w = h + l, residual <= 2^-22 |w|),
// spikes -> fp16 (exact: values are {0,1}).
// ---------------------------------------------------------------------------
__device__ __forceinline__ uint32_t pack_h16(__half lo, __half hi) {
    return (uint32_t)__half_as_ushort(lo) | ((uint32_t)__half_as_ushort(hi) << 16);
}

__global__ void pack_a_kernel(const float* __restrict__ A) {
    int i = blockIdx.x * blockDim.x + threadIdx.x;      // pair index
    float2 v = *(const float2*)(A + (size_t)i * 2);
    g_Apk[i] = pack_h16(__float2half_rn(v.x), __float2half_rn(v.y));
}

__global__ void pack_w_kernel(const float* __restrict__ W) {
    int i = blockIdx.x * blockDim.x + threadIdx.x;      // pair index
    float2 v = *(const float2*)(W + (size_t)i * 2);
    __half h0 = __float2half_rn(v.x);
    __half l0 = __float2half_rn(v.x - __half2float(h0));   // w-h exact in fp32
    __half h1 = __float2half_rn(v.y);
    __half l1 = __float2half_rn(v.y - __half2float(h1));
    g_Wh[i] = pack_h16(h0, h1);
    g_Wl[i] = pack_h16(l0, l1);
}

// ---------------------------------------------------------------------------
// GEMM: g_delta = spikes @ W^T + b   via fp16 m16n8k16 tensor cores.
// Hi plane: f32-acc mma, KC=32 flush (bit-proven path, unchanged).
// Lo plane: f16-acc mma (tiny magnitudes, ~2e-6 added noise), folded to the
// same fp32 sums every 2 k-tiles — testing whether the fallback HMMA runs
// f16-acc at 2x rate.
// CTA 128x128x32, 256 threads, 8 warps (2 along M x 4 along N), warp 64x32.
// ---------------------------------------------------------------------------
#define BM 128
#define BN 128
#define BK 32
#define BKP (BK / 2)     // 16 u32 per row per k-tile
#define STRU 20          // u32 row stride (16 + 4 pad) — ldmatrix conflict-free
#define TILE_U32 (BM * STRU)

__device__ __forceinline__ void mma_f16(float c[4], const uint32_t a[4], const uint32_t b[2]) {
    asm volatile(
        "mma.sync.aligned.m16n8k16.row.col.f32.f16.f16.f32 "
        "{%0,%1,%2,%3}, {%4,%5,%6,%7}, {%8,%9}, {%0,%1,%2,%3};\n"
        : "+f"(c[0]), "+f"(c[1]), "+f"(c[2]), "+f"(c[3])
        : "r"(a[0]), "r"(a[1]), "r"(a[2]), "r"(a[3]),
          "r"(b[0]), "r"(b[1]));
}

// D = A*B + 0  (fresh f32 accumulator, no zeroing MOVs)
__device__ __forceinline__ void mma_f16_zc(float d[4], const uint32_t a[4], const uint32_t b[2]) {
    asm volatile(
        "mma.sync.aligned.m16n8k16.row.col.f32.f16.f16.f32 "
        "{%0,%1,%2,%3}, {%4,%5,%6,%7}, {%8,%9}, {%10,%10,%10,%10};\n"
        : "=f"(d[0]), "=f"(d[1]), "=f"(d[2]), "=f"(d[3])
        : "r"(a[0]), "r"(a[1]), "r"(a[2]), "r"(a[3]),
          "r"(b[0]), "r"(b[1]), "f"(0.0f));
}

// f16-accumulator variants: D,C are 2x f16x2 registers
__device__ __forceinline__ void mma_f16h(uint32_t c[2], const uint32_t a[4], const uint32_t b[2]) {
    asm volatile(
        "mma.sync.aligned.m16n8k16.row.col.f16.f16.f16.f16 "
        "{%0,%1}, {%2,%3,%4,%5}, {%6,%7}, {%0,%1};\n"
        : "+r"(c[0]), "+r"(c[1])
        : "r"(a[0]), "r"(a[1]), "r"(a[2]), "r"(a[3]),
          "r"(b[0]), "r"(b[1]));
}

__device__ __forceinline__ void mma_f16h_zc(uint32_t d[2], const uint32_t a[4], const uint32_t b[2]) {
    asm volatile(
        "mma.sync.aligned.m16n8k16.row.col.f16.f16.f16.f16 "
        "{%0,%1}, {%2,%3,%4,%5}, {%6,%7}, {%8,%8};\n"
        : "=r"(d[0]), "=r"(d[1])
        : "r"(a[0]), "r"(a[1]), "r"(a[2]), "r"(a[3]),
          "r"(b[0]), "r"(b[1]), "r"(0u));
}

__device__ __forceinline__ void ldsm_x4(uint32_t d[4], uint32_t saddr) {
    asm volatile(
        "ldmatrix.sync.aligned.m8n8.x4.shared.b16 {%0,%1,%2,%3}, [%4];\n"
        : "=r"(d[0]), "=r"(d[1]), "=r"(d[2]), "=r"(d[3])
        : "r"(saddr));
}

__global__ __launch_bounds__(256, 1) void gemm_tc_kernel(const float* __restrict__ bias)
{
    __shared__ uint32_t As[TILE_U32];
    __shared__ uint32_t Bs[2][TILE_U32];

    const int tid  = threadIdx.x;
    const int m0   = blockIdx.y * BM;
    const int n0   = blockIdx.x * BN;

    const int lane = tid & 31;
    const int warp = tid >> 5;
    const int wm   = warp & 1;      // 2 warps along M
    const int wn   = warp >> 1;     // 4 warps along N
    const int warp_m = wm * 64;
    const int warp_n = wn * 32;
    const int g    = lane >> 2;     // 0..7
    const int t    = lane & 3;      // 0..3

    float    acc [4][4][4];         // hi-plane chunk accumulator (f32, one k-tile)
    uint32_t lacc[4][4][2];         // lo-plane accumulator (f16x2, two k-tiles)
    float    sum [4][4][4];         // IEEE running sum
#pragma unroll
    for (int i = 0; i < 4; i++)
#pragma unroll
        for (int j = 0; j < 4; j++)
#pragma unroll
            for (int r = 0; r < 4; r++) sum[i][j][r] = 0.0f;

    // shared-state-space byte addresses for ldmatrix
    const uint32_t as_base  = (uint32_t)__cvta_generic_to_shared(As);
    const uint32_t bs_base0 = (uint32_t)__cvta_generic_to_shared(Bs[0]);
    const uint32_t bs_base1 = (uint32_t)__cvta_generic_to_shared(Bs[1]);

    const int lrow16 = lane & 15;
    const int khalf  = (lane >> 4) * 16;   // bytes

    // global-load mapping: row = tid>>1 (0..127), q selects 8-u32 half of row
    const int grow = tid >> 1;
    const int q8   = (tid & 1) * 8;

    const uint32_t* gA = g_Apk + (size_t)(m0 + grow) * KP + q8;
    const uint32_t* gH = g_Wh  + (size_t)(n0 + grow) * KP + q8;
    const uint32_t* gL = g_Wl  + (size_t)(n0 + grow) * KP + q8;

    const int srow = grow * STRU + q8;

    // prefetch tile 0
    uint4 pa0 = *(const uint4*)(gA);   uint4 pa1 = *(const uint4*)(gA + 4);
    uint4 ph0 = *(const uint4*)(gH);   uint4 ph1 = *(const uint4*)(gH + 4);
    uint4 pl0 = *(const uint4*)(gL);   uint4 pl1 = *(const uint4*)(gL + 4);

    const int NKT = K_DIM / BK;   // 32
    for (int kt = 0; kt < NKT; kt++) {
        *(uint4*)(As    + srow) = pa0;  *(uint4*)(As    + srow + 4) = pa1;
        *(uint4*)(Bs[0] + srow) = ph0;  *(uint4*)(Bs[0] + srow + 4) = ph1;
        *(uint4*)(Bs[1] + srow) = pl0;  *(uint4*)(Bs[1] + srow + 4) = pl1;
        __syncthreads();

        // prefetch next tile into regs
        if (kt + 1 < NKT) {
            const int off = (kt + 1) * BKP;
            pa0 = *(const uint4*)(gA + off);  pa1 = *(const uint4*)(gA + off + 4);
            ph0 = *(const uint4*)(gH + off);  ph1 = *(const uint4*)(gH + off + 4);
            pl0 = *(const uint4*)(gL + off);  pl1 = *(const uint4*)(gL + off + 4);
        }

        // compute: two K=16 steps per tile, ldmatrix fragment loads
#pragma unroll
        for (int kkp = 0; kkp < BKP; kkp += 8) {
            const uint32_t kbyte = kkp * 4 + khalf;

            uint32_t af[4][4];
#pragma unroll
            for (int i = 0; i < 4; i++) {
                uint32_t addr = as_base + (uint32_t)(warp_m + i * 16 + lrow16) * (STRU * 4) + kbyte;
                ldsm_x4(af[i], addr);
            }

            uint32_t bf[2][4][2];   // [plane][n-frag][reg]
#pragma unroll
            for (int p = 0; p < 2; p++) {    // n-frag pairs (covers frags 2p, 2p+1)
                uint32_t nrow = (uint32_t)(warp_n + p * 16 + lrow16) * (STRU * 4) + kbyte;
                uint32_t d0[4], d1[4];
                ldsm_x4(d0, bs_base0 + nrow);
                ldsm_x4(d1, bs_base1 + nrow);
                bf[0][2 * p    ][0] = d0[0];  bf[0][2 * p    ][1] = d0[2];
                bf[0][2 * p + 1][0] = d0[1];  bf[0][2 * p + 1][1] = d0[3];
                bf[1][2 * p    ][0] = d1[0];  bf[1][2 * p    ][1] = d1[2];
                bf[1][2 * p + 1][0] = d1[1];  bf[1][2 * p + 1][1] = d1[3];
            }

            // hi plane: f32 accumulator, fresh (C=0) at first k-step of k-tile
            if (kkp == 0) {
#pragma unroll
                for (int i = 0; i < 4; i++)
#pragma unroll
                    for (int j = 0; j < 4; j++)
                        mma_f16_zc(acc[i][j], af[i], bf[0][j]);
            } else {
#pragma unroll
                for (int i = 0; i < 4; i++)
#pragma unroll
                    for (int j = 0; j < 4; j++)
                        mma_f16(acc[i][j], af[i], bf[0][j]);
            }

            // lo plane: f16 accumulator, fresh every 2 k-tiles
            if ((kt & 1) == 0 && kkp == 0) {
#pragma unroll
                for (int i = 0; i < 4; i++)
#pragma unroll
                    for (int j = 0; j < 4; j++)
                        mma_f16h_zc(lacc[i][j], af[i], bf[1][j]);
            } else {
#pragma unroll
                for (int i = 0; i < 4; i++)
#pragma unroll
                    for (int j = 0; j < 4; j++)
                        mma_f16h(lacc[i][j], af[i], bf[1][j]);
            }
        }

        // hi flush EVERY k-tile (KC = 32): IEEE RN adds
#pragma unroll
        for (int i = 0; i < 4; i++)
#pragma unroll
            for (int j = 0; j < 4; j++)
#pragma unroll
                for (int r = 0; r < 4; r++)
                    sum[i][j][r] += acc[i][j][r];

        // lo flush every 2 k-tiles: f16x2 -> f32, IEEE adds
        if (kt & 1) {
#pragma unroll
            for (int i = 0; i < 4; i++)
#pragma unroll
                for (int j = 0; j < 4; j++) {
                    float2 f01 = __half22float2(*(__half2*)&lacc[i][j][0]);
                    float2 f23 = __half22float2(*(__half2*)&lacc[i][j][1]);
                    sum[i][j][0] += f01.x;
                    sum[i][j][1] += f01.y;
                    sum[i][j][2] += f23.x;
                    sum[i][j][3] += f23.y;
                }
        }
        __syncthreads();
    }

    // epilogue: + bias (single fp32 add), float2 stores
#pragma unroll
    for (int i = 0; i < 4; i++) {
        int row0 = m0 + warp_m + i * 16 + g;
#pragma unroll
        for (int j = 0; j < 4; j++) {
            int col = n0 + warp_n + j * 8 + t * 2;
            float b0 = __ldg(bias + col);
            float b1 = __ldg(bias + col + 1);
            float2 lo = make_float2(sum[i][j][0] + b0, sum[i][j][1] + b1);
            float2 hi = make_float2(sum[i][j][2] + b0, sum[i][j][3] + b1);
            *(float2*)(g_delta + (size_t)row0       * N_DIM + col) = lo;
            *(float2*)(g_delta + (size_t)(row0 + 8) * N_DIM + col) = hi;
        }
    }
}

// ---------------- Scan over T: scalar per element, batched loads ------------
// out layout: [ ss (T*B*N) | mem_out (B*N) | hat_s (B*N) ]  all fp32
__global__ void scan_kernel(const float* __restrict__ mem_in,
                            float* __restrict__ out)
{
    const int j = blockIdx.x * blockDim.x + threadIdx.x;   // 0 .. 65535
    const int BN_ELEMS = BATCH * N_DIM;                    // 65536

    float m = mem_in[j];
    float ssum = 0.0f;

    for (int t0 = 0; t0 < T_STEPS; t0 += 20) {
        float buf[20];
#pragma unroll
        for (int u = 0; u < 20; u++)            // MLP = 20 loads in flight
            buf[u] = g_delta[(size_t)(t0 + u) * BN_ELEMS + j];
#pragma unroll
        for (int u = 0; u < 20; u++) {
            m += buf[u];
            float s = (m > THR) ? 1.0f : 0.0f;
            m = fminf(fmaxf(m, 0.0f), THR);     // clip(0, thr)
            m = m - m * s;                      // reset fired neurons
            out[(size_t)(t0 + u) * BN_ELEMS + j] = s;
            ssum += s;                          // integer-valued, exact
        }
    }

    const size_t ss_total = (size_t)T_STEPS * BN_ELEMS;
    out[ss_total + j]            = m;                      // mem_out
    out[ss_total + BN_ELEMS + j] = ssum / (float)T_STEPS;  // hat_s
}

// ---------------------------------------------------------------------------
extern "C" void kernel_launch(void* const* d_in, const int* in_sizes, int n_in,
                              void* d_out, int out_size)
{
    const float* spikes = (const float*)d_in[0];   // [100,64,1024]
    const float* mem    = (const float*)d_in[1];   // [64,1024]
    // d_in[2] = hat_spikes: numerically dead in the forward pass
    const float* W      = (const float*)d_in[3];   // [1024,1024]
    const float* b      = (const float*)d_in[4];   // [1024]
    float* out          = (float*)d_out;

    pack_a_kernel<<<(M_DIM * KP) / 256, 256>>>(spikes);
    pack_w_kernel<<<(N_DIM * KP) / 256, 256>>>(W);

    dim3 grid(N_DIM / BN, M_DIM / BM);   // (8, 50)
    gemm_tc_kernel<<<grid, 256>>>(b);

    scan_kernel<<<(BATCH * N_DIM) / 256, 256>>>(mem, out);
}